// round 2
// baseline (speedup 1.0000x reference)
#include <cuda_runtime.h>
#include <cstdint>

// ---------------- configuration ----------------
#define MT 128            // tokens per block tile
#define NT 128            // output cols per block tile
#define KT 16             // k-depth per smem stage
#define AST (KT + 4)      // A smem row stride (20 words) -> conflict-free frag reads
#define BST (NT + 8)      // B smem row stride (136 words) -> conflict-free frag reads
#define MAXTOK 32768
#define DOUT 1024

// ---------------- device scratch (no allocs allowed) ----------------
__device__ int g_cnt[4];
__device__ int g_idx[4 * MAXTOK];

// ---------------- bucketing ----------------
__global__ void zero_cnt_kernel() {
    if (threadIdx.x < 4) g_cnt[threadIdx.x] = 0;
}

__global__ void bucket_kernel(const int* __restrict__ tok,
                              const int* __restrict__ cat, int n) {
    int t = blockIdx.x * blockDim.x + threadIdx.x;
    if (t < n) {
        int c = __ldg(&cat[tok[t]]);
        int p = atomicAdd(&g_cnt[c], 1);
        g_idx[c * MAXTOK + p] = t;
    }
}

// fp32 -> tf32 (round-to-nearest) while staging into smem: free accuracy
__device__ __forceinline__ unsigned f2tf(float f) {
    unsigned u;
    asm("cvt.rna.tf32.f32 %0, %1;" : "=r"(u) : "f"(f));
    return u;
}

// ---------------- grouped GEMM: Y = gather(E, vocab_id) @ W + b ----------------
__global__ void __launch_bounds__(256)
gemm_kernel(const int* __restrict__ tok,
            const float* __restrict__ E0, const float* __restrict__ W0, const float* __restrict__ B0,
            const float* __restrict__ E1, const float* __restrict__ W1, const float* __restrict__ B1,
            const float* __restrict__ E2, const float* __restrict__ W2, const float* __restrict__ B2,
            const float* __restrict__ E3, const float* __restrict__ W3, const float* __restrict__ B3,
            float* __restrict__ out, int ntok)
{
    const int c   = blockIdx.z;
    const int cnt = g_cnt[c];
    const int m0  = blockIdx.y * MT;
    if (m0 >= cnt) return;
    const int n0  = blockIdx.x * NT;

    const float *E, *W, *BV; int dk;
    switch (c) {
        case 0:  E = E0; W = W0; BV = B0; dk = 1536; break;
        case 1:  E = E1; W = W1; BV = B1; dk = 1024; break;
        case 2:  E = E2; W = W2; BV = B2; dk = 512;  break;
        default: E = E3; W = W3; BV = B3; dk = 256;  break;
    }

    __shared__ __align__(16) unsigned As[2][MT][AST];
    __shared__ __align__(16) unsigned Bs[2][KT][BST];
    __shared__ int   s_pos[MT];   // output row (flattened token position)
    __shared__ int   s_vid[MT];   // vocab id (embedding gather row)
    __shared__ float s_bias[NT];

    const int tid = threadIdx.x;
    if (tid < MT) {
        int m = m0 + tid;
        int p = g_idx[c * MAXTOK + (m < cnt ? m : m0)];
        s_pos[tid] = p;
        s_vid[tid] = __ldg(&tok[p]);   // <-- vocab id, NOT position
    } else {
        s_bias[tid - MT] = BV[n0 + (tid - MT)];
    }
    __syncthreads();

    // per-thread global-load slots: 2 x float4 for A, 2 x float4 for B per stage
    int rowA[2], colA[2], rowB[2], colB[2];
    const float* aPtr[2];
    const float* bPtr[2];
#pragma unroll
    for (int j = 0; j < 2; j++) {
        int q = tid + j * 256;
        rowA[j] = q >> 2;  colA[j] = (q & 3) << 2;            // 128 rows x 16 cols
        aPtr[j] = E + (size_t)s_vid[rowA[j]] * dk + colA[j];
        rowB[j] = q >> 5;  colB[j] = (q & 31) << 2;           // 16 rows x 128 cols
        bPtr[j] = W + (size_t)rowB[j] * DOUT + n0 + colB[j];
    }

    const int lane = tid & 31, warp = tid >> 5;
    const int g = lane >> 2, t4 = lane & 3;
    const int wm = (warp & 3) * 32;   // 4 warps along M
    const int wn = (warp >> 2) * 64;  // 2 warps along N

    float acc[2][8][4];
#pragma unroll
    for (int mi = 0; mi < 2; mi++)
#pragma unroll
        for (int nf = 0; nf < 8; nf++)
#pragma unroll
            for (int r = 0; r < 4; r++) acc[mi][nf][r] = 0.f;

    const int nK = dk / KT;
    float4 ra[2], rb[2];

    // prologue: stage k-tile 0
#pragma unroll
    for (int j = 0; j < 2; j++) {
        ra[j] = *(const float4*)(aPtr[j]);
        rb[j] = *(const float4*)(bPtr[j]);
    }
#pragma unroll
    for (int j = 0; j < 2; j++) {
        *(uint4*)&As[0][rowA[j]][colA[j]] =
            make_uint4(f2tf(ra[j].x), f2tf(ra[j].y), f2tf(ra[j].z), f2tf(ra[j].w));
        *(uint4*)&Bs[0][rowB[j]][colB[j]] =
            make_uint4(f2tf(rb[j].x), f2tf(rb[j].y), f2tf(rb[j].z), f2tf(rb[j].w));
    }
    __syncthreads();

    for (int kt = 0; kt < nK; kt++) {
        const int cur = kt & 1;
        if (kt + 1 < nK) {
            const int k0 = (kt + 1) * KT;
#pragma unroll
            for (int j = 0; j < 2; j++) {
                ra[j] = *(const float4*)(aPtr[j] + k0);
                rb[j] = *(const float4*)(bPtr[j] + (size_t)k0 * DOUT);
            }
        }
        // compute current stage: 2 k8 steps
#pragma unroll
        for (int kk = 0; kk < KT; kk += 8) {
            unsigned a[2][4], b[8][2];
#pragma unroll
            for (int mi = 0; mi < 2; mi++) {
                int r = wm + mi * 16 + g;
                a[mi][0] = As[cur][r    ][kk + t4];
                a[mi][1] = As[cur][r + 8][kk + t4];
                a[mi][2] = As[cur][r    ][kk + t4 + 4];
                a[mi][3] = As[cur][r + 8][kk + t4 + 4];
            }
#pragma unroll
            for (int nf = 0; nf < 8; nf++) {
                b[nf][0] = Bs[cur][kk + t4    ][wn + nf * 8 + g];
                b[nf][1] = Bs[cur][kk + t4 + 4][wn + nf * 8 + g];
            }
#pragma unroll
            for (int mi = 0; mi < 2; mi++)
#pragma unroll
                for (int nf = 0; nf < 8; nf++)
                    asm volatile(
                        "mma.sync.aligned.m16n8k8.row.col.f32.tf32.tf32.f32 "
                        "{%0,%1,%2,%3},{%4,%5,%6,%7},{%8,%9},{%0,%1,%2,%3};"
                        : "+f"(acc[mi][nf][0]), "+f"(acc[mi][nf][1]),
                          "+f"(acc[mi][nf][2]), "+f"(acc[mi][nf][3])
                        : "r"(a[mi][0]), "r"(a[mi][1]), "r"(a[mi][2]), "r"(a[mi][3]),
                          "r"(b[nf][0]), "r"(b[nf][1]));
        }
        if (kt + 1 < nK) {
            const int nxt = cur ^ 1;
#pragma unroll
            for (int j = 0; j < 2; j++) {
                *(uint4*)&As[nxt][rowA[j]][colA[j]] =
                    make_uint4(f2tf(ra[j].x), f2tf(ra[j].y), f2tf(ra[j].z), f2tf(ra[j].w));
                *(uint4*)&Bs[nxt][rowB[j]][colB[j]] =
                    make_uint4(f2tf(rb[j].x), f2tf(rb[j].y), f2tf(rb[j].z), f2tf(rb[j].w));
            }
        }
        __syncthreads();
    }

    // epilogue: add bias, scatter rows to out[token_position]
#pragma unroll
    for (int mi = 0; mi < 2; mi++) {
        int r = wm + mi * 16 + g;
        bool ok0 = (m0 + r)     < cnt;
        bool ok1 = (m0 + r + 8) < cnt;
        long t0 = ok0 ? s_pos[r]     : 0;
        long t1 = ok1 ? s_pos[r + 8] : 0;
#pragma unroll
        for (int nf = 0; nf < 8; nf++) {
            int col = wn + nf * 8 + t4 * 2;
            float b0 = s_bias[col], b1 = s_bias[col + 1];
            if (ok0) {
                float2 v = make_float2(acc[mi][nf][0] + b0, acc[mi][nf][1] + b1);
                *(float2*)(out + t0 * DOUT + n0 + col) = v;
            }
            if (ok1) {
                float2 v = make_float2(acc[mi][nf][2] + b0, acc[mi][nf][3] + b1);
                *(float2*)(out + t1 * DOUT + n0 + col) = v;
            }
        }
    }
}

// ---------------- launch ----------------
extern "C" void kernel_launch(void* const* d_in, const int* in_sizes, int n_in,
                              void* d_out, int out_size) {
    const int*   tok = (const int*)d_in[0];
    const int*   cat = (const int*)d_in[1];
    const float* E0 = (const float*)d_in[2];
    const float* W0 = (const float*)d_in[3];
    const float* B0 = (const float*)d_in[4];
    const float* E1 = (const float*)d_in[5];
    const float* W1 = (const float*)d_in[6];
    const float* B1 = (const float*)d_in[7];
    const float* E2 = (const float*)d_in[8];
    const float* W2 = (const float*)d_in[9];
    const float* B2 = (const float*)d_in[10];
    const float* E3 = (const float*)d_in[11];
    const float* W3 = (const float*)d_in[12];
    const float* B3 = (const float*)d_in[13];
    float* out = (float*)d_out;

    int n = in_sizes[0];  // 32768 tokens

    zero_cnt_kernel<<<1, 32>>>();
    bucket_kernel<<<(n + 255) / 256, 256>>>(tok, cat, n);

    // n-tile fastest so the 8 n-tiles sharing an A m-tile co-schedule (L2 reuse)
    dim3 grid(DOUT / NT, (n + MT - 1) / MT, 4);
    gemm_kernel<<<grid, 256>>>(tok, E0, W0, B0, E1, W1, B1, E2, W2, B2,
                               E3, W3, B3, out, n);
}